// round 16
// baseline (speedup 1.0000x reference)
#include <cuda_runtime.h>
#include <cuda_bf16.h>
#include <cuda_fp16.h>
#include <math.h>
#include <stdint.h>

#define NA 131072
#define NC 32768
#define BB 128
#define MM 256
#define EE 262144
#define DD 256
#define HH 8
#define CC 32
#define PEK 64
#define Q3 (3 * DD)

// ---------------- scratch ----------------
__device__ float g_pe[NC * DD];
__device__ float g_hx[NC * DD];
__device__ float g_cx0[NC * DD];
__device__ float g_o2[NC * DD];
__device__ float g_score[NC * HH];
__device__ int g_cnt[NC];
__device__ int g_off[NC + 1];
__device__ int g_cur[NC];
__device__ int g_adj[EE];
__device__ int g_bsum[32];
__device__ unsigned g_bar;
__device__ __half g_ape16[NC * PEK];
__device__ __half g_wpe16[DD * PEK];
__device__ __half g_agg16[NC * DD];
__device__ __half g_watom16[DD * DD];
__device__ __half g_acx16[NC * DD];
__device__ __half g_win16[3 * DD * DD];
__device__ __half g_qkv16[NC * Q3];
__device__ __half g_ao16[NC * DD];
__device__ __half g_wout16[DD * DD];

// ---------------- block reductions (256 threads) ----------------
__device__ __forceinline__ float blk_sum(float v, float* sh8) {
    int t = threadIdx.x;
    int lane = t & 31, w = t >> 5;
#pragma unroll
    for (int o = 16; o > 0; o >>= 1) v += __shfl_xor_sync(0xffffffffu, v, o);
    if (lane == 0) sh8[w] = v;
    __syncthreads();
    float tot = sh8[0];
#pragma unroll
    for (int i = 1; i < 8; i++) tot += sh8[i];
    __syncthreads();
    return tot;
}

// 512-thread variants
__device__ __forceinline__ float blk_sum16(float v, float* sh16) {
    int t = threadIdx.x;
    int lane = t & 31, w = t >> 5;
#pragma unroll
    for (int o = 16; o > 0; o >>= 1) v += __shfl_xor_sync(0xffffffffu, v, o);
    if (lane == 0) sh16[w] = v;
    __syncthreads();
    float tot = sh16[0];
#pragma unroll
    for (int i = 1; i < 16; i++) tot += sh16[i];
    __syncthreads();
    return tot;
}

__device__ __forceinline__ float blk_max16(float v, float* sh16) {
    int t = threadIdx.x;
    int lane = t & 31, w = t >> 5;
#pragma unroll
    for (int o = 16; o > 0; o >>= 1) v = fmaxf(v, __shfl_xor_sync(0xffffffffu, v, o));
    if (lane == 0) sh16[w] = v;
    __syncthreads();
    float tot = sh16[0];
#pragma unroll
    for (int i = 1; i < 16; i++) tot = fmaxf(tot, sh16[i]);
    __syncthreads();
    return tot;
}

__device__ __forceinline__ uint32_t pack_h2(float a, float b) {
    __half2 h = __floats2half2_rn(a, b);
    return *(uint32_t*)&h;
}

// ---------------- fused weight/pe conversion + cnt/bar zeroing ----------------
__global__ void k_split_all(const float* __restrict__ pe_w, const float* __restrict__ atom_w,
                            const float* __restrict__ in_w, const float* __restrict__ out_w,
                            const float* __restrict__ clique_pe) {
    int i = blockIdx.x * 256 + threadIdx.x;
    if (i == 0) g_bar = 0u;
    if (i < NC) g_cnt[i] = 0;
    const int n0 = DD * PEK;
    const int n1 = n0 + DD * DD;
    const int n2 = n1 + 3 * DD * DD;
    const int n3 = n2 + DD * DD;
    const int n4 = n3 + NC * PEK;
    if (i >= n4) return;
    if (i < n0) {
        int r = i / PEK, c = i % PEK;
        float v = (c < 20) ? pe_w[r * 20 + c] : 0.f;
        g_wpe16[i] = __float2half(v);
    } else if (i < n1) g_watom16[i - n0] = __float2half(atom_w[i - n0]);
    else if (i < n2) g_win16[i - n1] = __float2half(in_w[i - n1]);
    else if (i < n3) g_wout16[i - n2] = __float2half(out_w[i - n2]);
    else {
        int j = i - n3;
        int r = j / PEK, c = j % PEK;
        float v = (c < 20) ? clique_pe[r * 20 + c] : 0.f;
        g_ape16[j] = __float2half(v);
    }
}

// ---------------- fused CSR build: count + scan + fill, 32 blocks x 1024 ----------------
__device__ __forceinline__ void grid_bar32(int target) {
    __syncthreads();
    __threadfence();
    if (threadIdx.x == 0) {
        atomicAdd(&g_bar, 1u);
        while (atomicAdd(&g_bar, 0u) < (unsigned)target) {}
    }
    __syncthreads();
}

__global__ void __launch_bounds__(1024) k_csr(const int* __restrict__ row,
                                              const int* __restrict__ col) {
    __shared__ int sh[1024];
    __shared__ int sboff, stot;
    int b = blockIdx.x, t = threadIdx.x;

    // phase 1: count (coalesced: 8 strided passes)
#pragma unroll
    for (int i = 0; i < 8; i++) {
        int e = i * 32768 + b * 1024 + t;
        atomicAdd(&g_cnt[col[e]], 1);
    }
    grid_bar32(32);

    // phase 2: per-block inclusive scan of 1024 counts
    int v = g_cnt[b * 1024 + t];
    sh[t] = v;
    __syncthreads();
    for (int off = 1; off < 1024; off <<= 1) {
        int u = (t >= off) ? sh[t - off] : 0;
        __syncthreads();
        sh[t] += u;
        __syncthreads();
    }
    int excl = sh[t] - v;
    if (t == 1023) g_bsum[b] = sh[t];
    grid_bar32(64);

    // phase 3: warp-scan block sums; apply offsets
    if (t < 32) {
        int bv = g_bsum[t];
        int inc = bv;
#pragma unroll
        for (int o = 1; o < 32; o <<= 1) {
            int u = __shfl_up_sync(0xffffffffu, inc, o);
            if (t >= o) inc += u;
        }
        if (t == b) sboff = inc - bv;
        if (t == 31) stot = inc;
    }
    __syncthreads();
    int val = excl + sboff;
    g_off[b * 1024 + t] = val;
    g_cur[b * 1024 + t] = val;
    if (b == 0 && t == 0) g_off[NC] = stot;
    grid_bar32(96);

    // phase 4: fill
#pragma unroll
    for (int i = 0; i < 8; i++) {
        int e = i * 32768 + b * 1024 + t;
        int c = col[e];
        int pos = atomicAdd(&g_cur[c], 1);
        g_adj[pos] = row[e];
    }
}

__global__ void __launch_bounds__(256) k_gather(const float* __restrict__ x) {
    __shared__ float red[4][DD];
    int c = blockIdx.x;
    int t = threadIdx.x;
    int lane4 = t & 63;
    int sl = t >> 6;
    int s = g_off[c], e2 = g_off[c + 1];
    float4 acc = {0.f, 0.f, 0.f, 0.f};
    for (int j = s + sl; j < e2; j += 4) {
        int r = g_adj[j];
        float4 v = *(const float4*)(x + (size_t)r * DD + lane4 * 4);
        acc.x += v.x; acc.y += v.y; acc.z += v.z; acc.w += v.w;
    }
    *(float4*)&red[sl][lane4 * 4] = acc;
    __syncthreads();
    float tot = red[0][t] + red[1][t] + red[2][t] + red[3][t];
    float dg = (float)(e2 - s);
    tot /= fmaxf(dg, 1.f);
    g_agg16[(size_t)c * DD + t] = __float2half(tot);
}

// ---------------- HMMA primitives ----------------
__device__ __forceinline__ void ldsm4(uint32_t& r0, uint32_t& r1, uint32_t& r2, uint32_t& r3,
                                      const void* p) {
    uint32_t addr = (uint32_t)__cvta_generic_to_shared(p);
    asm volatile("ldmatrix.sync.aligned.m8n8.x4.shared.b16 {%0,%1,%2,%3}, [%4];"
                 : "=r"(r0), "=r"(r1), "=r"(r2), "=r"(r3)
                 : "r"(addr));
}

__device__ __forceinline__ void mma16816h(float* d, const uint32_t* a, const uint32_t* b) {
    asm volatile(
        "mma.sync.aligned.m16n8k16.row.col.f32.f16.f16.f32 "
        "{%0,%1,%2,%3},{%4,%5,%6,%7},{%8,%9},{%0,%1,%2,%3};"
        : "+f"(d[0]), "+f"(d[1]), "+f"(d[2]), "+f"(d[3])
        : "r"(a[0]), "r"(a[1]), "r"(a[2]), "r"(a[3]), "r"(b[0]), "r"(b[1]));
}

#define CP16(dst, src) \
    asm volatile("cp.async.cg.shared.global [%0], [%1], 16;" :: "r"(dst), "l"(src) : "memory")
#define CP_COMMIT() asm volatile("cp.async.commit_group;" ::: "memory")
#define CP_WAIT0() asm volatile("cp.async.wait_group 0;" ::: "memory")

#define SST 72
#define GEMM_SMEM (2 * 2 * 128 * SST * 2)

// ---------------- fp16 single-pass GEMM core (K-chunk 64) ----------------
__device__ __forceinline__ void gemm16_body(
    const __half* __restrict__ A, const __half* __restrict__ W,
    const float* __restrict__ bias, float* __restrict__ C,
    __half* __restrict__ Ch, int M, int K, int i0, int j0, __half* sbuf) {
    uint32_t sbase = (uint32_t)__cvta_generic_to_shared(sbuf);
    int tid = threadIdx.x;
    int lane = tid & 31, wid = tid >> 5;
    int wm = wid >> 2, wn = wid & 3;
    int mb = wm * 32, nb = wn * 32;

    float d[2][4][4];
#pragma unroll
    for (int mi = 0; mi < 2; mi++)
#pragma unroll
        for (int ni = 0; ni < 4; ni++)
#pragma unroll
            for (int e = 0; e < 4; e++) d[mi][ni][e] = 0.f;

    int nch = K >> 6;

#pragma unroll
    for (int i = 0; i < 4; i++) {
        int task = tid + i * 512;
        int ck = task & 7;
        int row = (task >> 3) & 127;
        int mat = task >> 10;
        const __half* src = mat ? (W + (size_t)(j0 + row) * K) : (A + (size_t)(i0 + row) * K);
        uint32_t dst = sbase + (uint32_t)((mat * 128 + row) * SST + ck * 8) * 2u;
        CP16(dst, src + ck * 8);
    }
    CP_COMMIT();

    for (int ch = 0; ch < nch; ch++) {
        int stage = ch & 1;
        CP_WAIT0();
        __syncthreads();
        if (ch + 1 < nch) {
            int kt = (ch + 1) << 6;
            int ns = (ch + 1) & 1;
#pragma unroll
            for (int i = 0; i < 4; i++) {
                int task = tid + i * 512;
                int ck = task & 7;
                int row = (task >> 3) & 127;
                int mat = task >> 10;
                const __half* src =
                    mat ? (W + (size_t)(j0 + row) * K) : (A + (size_t)(i0 + row) * K);
                uint32_t dst =
                    sbase + (uint32_t)(((ns * 2 + mat) * 128 + row) * SST + ck * 8) * 2u;
                CP16(dst, src + kt + ck * 8);
            }
            CP_COMMIT();
        }

        const __half* tA = sbuf + (stage * 2 + 0) * 128 * SST;
        const __half* tW = sbuf + (stage * 2 + 1) * 128 * SST;

#pragma unroll
        for (int ks = 0; ks < 4; ks++) {
            int k0 = ks * 16;
            uint32_t afr[2][4];
            uint32_t bfr[4][2];
#pragma unroll
            for (int mi = 0; mi < 2; mi++) {
                const __half* p =
                    tA + (mb + mi * 16 + (lane & 15)) * SST + k0 + (lane >> 4) * 8;
                ldsm4(afr[mi][0], afr[mi][1], afr[mi][2], afr[mi][3], p);
            }
#pragma unroll
            for (int np = 0; np < 2; np++) {
                const __half* p =
                    tW + (nb + np * 16 + (lane & 7) + ((lane >> 4) << 3)) * SST + k0 +
                    (((lane >> 3) & 1) << 3);
                uint32_t r0, r1, r2, r3;
                ldsm4(r0, r1, r2, r3, p);
                bfr[np * 2][0] = r0; bfr[np * 2][1] = r1;
                bfr[np * 2 + 1][0] = r2; bfr[np * 2 + 1][1] = r3;
            }
#pragma unroll
            for (int mi = 0; mi < 2; mi++)
#pragma unroll
                for (int ni = 0; ni < 4; ni++) mma16816h(d[mi][ni], afr[mi], bfr[ni]);
        }
        __syncthreads();
    }

#pragma unroll
    for (int mi = 0; mi < 2; mi++) {
#pragma unroll
        for (int ni = 0; ni < 4; ni++) {
            int row = i0 + mb + mi * 16 + (lane >> 2);
            int colc = j0 + nb + ni * 8 + (lane & 3) * 2;
            float b0 = bias ? bias[colc] : 0.f;
            float b1 = bias ? bias[colc + 1] : 0.f;
            float v00 = d[mi][ni][0] + b0, v01 = d[mi][ni][1] + b1;
            float v10 = d[mi][ni][2] + b0, v11 = d[mi][ni][3] + b1;
            size_t ix = (size_t)row * M + colc;
            size_t ix2 = ix + (size_t)8 * M;
            if (Ch) {
                *(uint32_t*)&Ch[ix] = pack_h2(v00, v01);
                *(uint32_t*)&Ch[ix2] = pack_h2(v10, v11);
            } else {
                C[ix] = v00;
                C[ix + 1] = v01;
                C[ix2] = v10;
                C[ix2 + 1] = v11;
            }
        }
    }
}

__global__ void __launch_bounds__(512, 2) k_gemm16(
    const __half* __restrict__ A, const __half* __restrict__ W,
    const float* __restrict__ bias, float* __restrict__ C,
    __half* __restrict__ Ch, int N, int M, int K) {
    extern __shared__ __half sbuf[];
    gemm16_body(A, W, bias, C, Ch, M, K, blockIdx.x * 128, blockIdx.y * 128, sbuf);
}

__global__ void __launch_bounds__(512, 2) k_gemm16_dual(
    const __half* __restrict__ Aat, const __half* __restrict__ Wat,
    const __half* __restrict__ Ape, const __half* __restrict__ Wpe) {
    extern __shared__ __half sbuf[];
    int y = blockIdx.y;
    if (y < 2) {
        gemm16_body(Aat, Wat, nullptr, g_hx, nullptr, DD, DD, blockIdx.x * 128, y * 128, sbuf);
    } else {
        gemm16_body(Ape, Wpe, nullptr, g_pe, nullptr, DD, PEK, blockIdx.x * 128,
                    (y - 2) * 128, sbuf);
    }
}

// ---------------- cx0 ----------------
__global__ void k_cx0(const float* __restrict__ clique_x,
                      const float* __restrict__ pe_g, const float* __restrict__ pe_b,
                      const float* __restrict__ atom_g, const float* __restrict__ atom_b) {
    __shared__ float sh8[8];
    int n = blockIdx.x, t = threadIdx.x;
    size_t idx = (size_t)n * DD + t;

    float pv = g_pe[idx];
    float mu = blk_sum(pv, sh8) * (1.f / DD);
    float dv = pv - mu;
    float var = blk_sum(dv * dv, sh8) * (1.f / DD);
    float pen = dv * rsqrtf(var + 1e-5f) * pe_g[t] + pe_b[t];

    float hv = g_hx[idx];
    mu = blk_sum(hv, sh8) * (1.f / DD);
    dv = hv - mu;
    var = blk_sum(dv * dv, sh8) * (1.f / DD);
    float hxn = dv * rsqrtf(var + 1e-5f) * atom_g[t] + atom_b[t];

    float v = clique_x[idx] + pen + hxn;
    g_cx0[idx] = v;
    g_acx16[idx] = __float2half(v);
}

// ---------------- fp16 single-pass flash attention ----------------
#define QS 40
#define VS 264
#define ATT_SMEM ((2 * 256 * QS + 32 * VS) * 2)

__global__ void __launch_bounds__(512, 2) k_attn_tc() {
    extern __shared__ __half smh[];
    __half* qh = smh;
    __half* kh = smh + 256 * QS;
    __half* vt = smh + 2 * 256 * QS;

    int bh = blockIdx.x, b = bh >> 3, hh = bh & 7;
    int t = threadIdx.x, lane = t & 31, w = t >> 5;
    int n0 = b * MM;

    {
        int j = t >> 1;
        int c0 = (t & 1) * 16;
        size_t src = (size_t)(n0 + j) * Q3 + hh * CC + c0;
        uint32_t dq = (uint32_t)__cvta_generic_to_shared(qh + j * QS + c0);
        uint32_t dk = (uint32_t)__cvta_generic_to_shared(kh + j * QS + c0);
        CP16(dq, g_qkv16 + src);
        CP16(dq + 16, g_qkv16 + src + 8);
        CP16(dk, g_qkv16 + src + DD);
        CP16(dk + 16, g_qkv16 + src + DD + 8);
        uint4 v0 = *(const uint4*)(g_qkv16 + src + 2 * DD);
        uint4 v1 = *(const uint4*)(g_qkv16 + src + 2 * DD + 8);
        const __half* vv0 = (const __half*)&v0;
        const __half* vv1 = (const __half*)&v1;
#pragma unroll
        for (int e = 0; e < 8; e++) {
            vt[(c0 + e) * VS + j] = vv0[e];
            vt[(c0 + 8 + e) * VS + j] = vv1[e];
        }
    }
    CP_COMMIT();
    CP_WAIT0();
    __syncthreads();

    int mb = w * 16;

    uint32_t aq[2][4];
#pragma unroll
    for (int ks = 0; ks < 2; ks++) {
        const __half* p = qh + (mb + (lane & 15)) * QS + ks * 16 + (lane >> 4) * 8;
        ldsm4(aq[ks][0], aq[ks][1], aq[ks][2], aq[ks][3], p);
    }

    float o[4][4];
#pragma unroll
    for (int ni = 0; ni < 4; ni++)
#pragma unroll
        for (int e = 0; e < 4; e++) o[ni][e] = 0.f;
    float mrow[2] = {-INFINITY, -INFINITY};
    float lrow[2] = {0.f, 0.f};

    const float scale = 0.17677669529663687f;

#pragma unroll 1
    for (int ck = 0; ck < 8; ck++) {
        float s[4][4];
#pragma unroll
        for (int nj = 0; nj < 4; nj++)
#pragma unroll
            for (int e = 0; e < 4; e++) s[nj][e] = 0.f;

#pragma unroll
        for (int ks = 0; ks < 2; ks++) {
            uint32_t bk[4][2];
#pragma unroll
            for (int np = 0; np < 2; np++) {
                const __half* p =
                    kh + (ck * 32 + np * 16 + (lane & 7) + ((lane >> 4) << 3)) * QS +
                    ks * 16 + (((lane >> 3) & 1) << 3);
                uint32_t r0, r1, r2, r3;
                ldsm4(r0, r1, r2, r3, p);
                bk[np * 2][0] = r0; bk[np * 2][1] = r1;
                bk[np * 2 + 1][0] = r2; bk[np * 2 + 1][1] = r3;
            }
#pragma unroll
            for (int nj = 0; nj < 4; nj++) mma16816h(s[nj], aq[ks], bk[nj]);
        }

#pragma unroll
        for (int rh = 0; rh < 2; rh++) {
            float cm = -INFINITY;
#pragma unroll
            for (int nj = 0; nj < 4; nj++) {
                s[nj][rh * 2] *= scale;
                s[nj][rh * 2 + 1] *= scale;
                cm = fmaxf(cm, fmaxf(s[nj][rh * 2], s[nj][rh * 2 + 1]));
            }
            cm = fmaxf(cm, __shfl_xor_sync(0xffffffffu, cm, 1));
            cm = fmaxf(cm, __shfl_xor_sync(0xffffffffu, cm, 2));
            float nm = fmaxf(mrow[rh], cm);
            float corr = __expf(mrow[rh] - nm);
            mrow[rh] = nm;
            float ps = 0.f;
#pragma unroll
            for (int nj = 0; nj < 4; nj++) {
                float p0 = __expf(s[nj][rh * 2] - nm);
                float p1 = __expf(s[nj][rh * 2 + 1] - nm);
                s[nj][rh * 2] = p0;
                s[nj][rh * 2 + 1] = p1;
                ps += p0 + p1;
            }
            lrow[rh] = lrow[rh] * corr + ps;
#pragma unroll
            for (int ni = 0; ni < 4; ni++) {
                o[ni][rh * 2] *= corr;
                o[ni][rh * 2 + 1] *= corr;
            }
        }

#pragma unroll
        for (int kk = 0; kk < 2; kk++) {
            uint32_t bv[4][2];
#pragma unroll
            for (int ng = 0; ng < 2; ng++) {
                const __half* p =
                    vt + (ng * 16 + (lane & 7) + ((lane >> 4) << 3)) * VS + ck * 32 +
                    kk * 16 + (((lane >> 3) & 1) << 3);
                uint32_t r0, r1, r2, r3;
                ldsm4(r0, r1, r2, r3, p);
                bv[ng * 2][0] = r0; bv[ng * 2][1] = r1;
                bv[ng * 2 + 1][0] = r2; bv[ng * 2 + 1][1] = r3;
            }
            uint32_t pa[4];
#pragma unroll
            for (int half = 0; half < 2; half++) {
                int nj = kk * 2 + half;
#pragma unroll
                for (int e = 0; e < 2; e++)
                    pa[half * 2 + e] = pack_h2(s[nj][e * 2], s[nj][e * 2 + 1]);
            }
#pragma unroll
            for (int ni = 0; ni < 4; ni++) mma16816h(o[ni], pa, bv[ni]);
        }
    }

    float linv[2];
#pragma unroll
    for (int rh = 0; rh < 2; rh++) {
        float l = lrow[rh];
        l += __shfl_xor_sync(0xffffffffu, l, 1);
        l += __shfl_xor_sync(0xffffffffu, l, 2);
        linv[rh] = 1.f / l;
    }

#pragma unroll
    for (int ni = 0; ni < 4; ni++) {
        int row = mb + (lane >> 2);
        int chc = hh * CC + ni * 8 + (lane & 3) * 2;
        size_t idx = (size_t)(n0 + row) * DD + chc;
        *(uint32_t*)&g_ao16[idx] = pack_h2(o[ni][0] * linv[0], o[ni][1] * linv[0]);
        *(uint32_t*)&g_ao16[idx + (size_t)8 * DD] =
            pack_h2(o[ni][2] * linv[1], o[ni][3] * linv[1]);
    }
}

// ---------------- cx = LN(cx0 + o2) ----------------
__global__ void k_cn(const float* __restrict__ cn_g, const float* __restrict__ cn_b,
                     float* __restrict__ cxp) {
    __shared__ float sh8[8];
    int n = blockIdx.x, t = threadIdx.x;
    size_t idx = (size_t)n * DD + t;
    float v = g_cx0[idx] + g_o2[idx];
    float mu = blk_sum(v, sh8) * (1.f / DD);
    float dv = v - mu;
    float var = blk_sum(dv * dv, sh8) * (1.f / DD);
    cxp[idx] = dv * rsqrtf(var + 1e-5f) * cn_g[t] + cn_b[t];
}

// ---------------- per-head MLP score ----------------
__global__ void __launch_bounds__(256) k_score2(const float* __restrict__ cxp,
                                                const float* __restrict__ mlp_w1,
                                                const float* __restrict__ mlp_b1,
                                                const float* __restrict__ mlp_w2,
                                                const float* __restrict__ mlp_b2) {
    extern __shared__ float w1s[];
    __shared__ float b1s[512], w2s[512], b2s[8];
    int t = threadIdx.x;
    for (int i = t; i < 16384; i += 256) w1s[i] = mlp_w1[i];
    for (int i = t; i < 512; i += 256) {
        b1s[i] = mlp_b1[i];
        w2s[i] = mlp_w2[i];
    }
    if (t < 8) b2s[t] = mlp_b2[t];
    __syncthreads();

    int h = t >> 5, lane = t & 31;
    int base = blockIdx.x * 128;
#pragma unroll 1
    for (int pass = 0; pass < 4; pass++) {
        int n = base + pass * 32 + lane;
        float sc[32];
        const float* p = cxp + (size_t)n * DD + h * 32;
#pragma unroll
        for (int c = 0; c < 32; c += 4) {
            float4 v4 = *(const float4*)(p + c);
            sc[c] = v4.x; sc[c + 1] = v4.y; sc[c + 2] = v4.z; sc[c + 3] = v4.w;
        }
        float ssum = b2s[h];
#pragma unroll 4
        for (int d = 0; d < 64; d++) {
            float a = b1s[h * 64 + d];
            const float4* wr4 = (const float4*)&w1s[(h * 64 + d) * 32];
#pragma unroll
            for (int cc = 0; cc < 8; cc++) {
                float4 wv = wr4[cc];
                a += sc[cc * 4] * wv.x + sc[cc * 4 + 1] * wv.y + sc[cc * 4 + 2] * wv.z +
                     sc[cc * 4 + 3] * wv.w;
            }
            a = fmaxf(a, 0.f);
            ssum += a * w2s[h * 64 + d];
        }
        g_score[(size_t)n * HH + h] = ssum;
    }
}

// ---------------- segment softmax + pooling (512 threads) ----------------
__global__ void __launch_bounds__(512) k_pool(const float* __restrict__ cxp,
                                              float* __restrict__ alphap,
                                              float* __restrict__ drug) {
    __shared__ float sh16[16];
    __shared__ float al[MM * HH];
    __shared__ float part[2][DD];
    int b = blockIdx.x, t = threadIdx.x;
    int tq = t & 255;
    int n = b * MM + tq;
    float sc[HH];
    if (t < 256) {
#pragma unroll
        for (int h = 0; h < HH; h++) sc[h] = g_score[(size_t)n * HH + h];
    } else {
#pragma unroll
        for (int h = 0; h < HH; h++) sc[h] = -INFINITY;
    }
#pragma unroll
    for (int h = 0; h < HH; h++) {
        float mx = blk_max16(sc[h], sh16);
        float e = (t < 256) ? expf(sc[h] - mx) : 0.f;
        float s = blk_sum16(e, sh16);
        if (t < 256) {
            float a = e / s;
            al[tq * HH + h] = a;
            alphap[(size_t)n * HH + h] = a;
        }
    }
    __syncthreads();
    int g = t >> 8;
    int ch = t & 255;
    int h = ch >> 5;
    float acc = 0.f;
    int q0 = g * 128;
    for (int q = q0; q < q0 + 128; q++)
        acc += cxp[((size_t)b * MM + q) * DD + ch] * al[q * HH + h];
    part[g][ch] = acc;
    __syncthreads();
    if (t < 256) drug[(size_t)b * DD + t] = part[0][t] + part[1][t];
}

// ---------------- launch ----------------
extern "C" void kernel_launch(void* const* d_in, const int* in_sizes, int n_in,
                              void* d_out, int out_size) {
    const float* x         = (const float*)d_in[0];
    const float* clique_x  = (const float*)d_in[1];
    const float* clique_pe = (const float*)d_in[2];
    const int*   row       = (const int*)d_in[3];
    const int*   col       = (const int*)d_in[4];
    const float* pe_w   = (const float*)d_in[6];
    const float* pe_g   = (const float*)d_in[7];
    const float* pe_b   = (const float*)d_in[8];
    const float* atom_w = (const float*)d_in[9];
    const float* atom_g = (const float*)d_in[10];
    const float* atom_b = (const float*)d_in[11];
    const float* in_w   = (const float*)d_in[12];
    const float* in_b   = (const float*)d_in[13];
    const float* out_w  = (const float*)d_in[14];
    const float* out_b  = (const float*)d_in[15];
    const float* cn_g   = (const float*)d_in[16];
    const float* cn_b   = (const float*)d_in[17];
    const float* mlp_w1 = (const float*)d_in[18];
    const float* mlp_b1 = (const float*)d_in[19];
    const float* mlp_w2 = (const float*)d_in[20];
    const float* mlp_b2 = (const float*)d_in[21];

    float* out = (float*)d_out;
    float* drug   = out;
    float* cxp    = out + (size_t)BB * DD;
    float* alphap = cxp + (size_t)NC * DD;

    float* p_o2;
    cudaGetSymbolAddress((void**)&p_o2, g_o2);
    __half *ape, *wpe, *agg, *wat, *acx, *win, *qkv, *ao, *wo;
    cudaGetSymbolAddress((void**)&ape, g_ape16);
    cudaGetSymbolAddress((void**)&wpe, g_wpe16);
    cudaGetSymbolAddress((void**)&agg, g_agg16);
    cudaGetSymbolAddress((void**)&wat, g_watom16);
    cudaGetSymbolAddress((void**)&acx, g_acx16);
    cudaGetSymbolAddress((void**)&win, g_win16);
    cudaGetSymbolAddress((void**)&qkv, g_qkv16);
    cudaGetSymbolAddress((void**)&ao, g_ao16);
    cudaGetSymbolAddress((void**)&wo, g_wout16);

    cudaFuncSetAttribute(k_score2, cudaFuncAttributeMaxDynamicSharedMemorySize, 65536);
    cudaFuncSetAttribute(k_gemm16, cudaFuncAttributeMaxDynamicSharedMemorySize, GEMM_SMEM);
    cudaFuncSetAttribute(k_gemm16_dual, cudaFuncAttributeMaxDynamicSharedMemorySize, GEMM_SMEM);
    cudaFuncSetAttribute(k_attn_tc, cudaFuncAttributeMaxDynamicSharedMemorySize, ATT_SMEM);
    cudaFuncSetAttribute(k_attn_tc, cudaFuncAttributePreferredSharedMemoryCarveout, 100);

    const int splitN = DD * PEK + DD * DD + 3 * DD * DD + DD * DD + NC * PEK;

    // 1. fused conversions + cnt/bar zero
    k_split_all<<<(splitN + 255) / 256, 256>>>(pe_w, atom_w, in_w, out_w, clique_pe);

    // 2. fused CSR build (count + scan + fill)
    k_csr<<<32, 1024>>>(row, col);

    // 3. gather-mean
    k_gather<<<NC, 256>>>(x);

    // 4. merged atom + pe GEMM
    k_gemm16_dual<<<dim3(NC / 128, 4), 512, GEMM_SMEM>>>(agg, wat, ape, wpe);

    // 5. cx0 (+ fp16 store)
    k_cx0<<<NC, 256>>>(clique_x, pe_g, pe_b, atom_g, atom_b);

    // 6. qkv GEMM — fp16 in/out
    k_gemm16<<<dim3(NC / 128, 6), 512, GEMM_SMEM>>>(acx, win, in_b, nullptr, qkv,
                                                    NC, 3 * DD, DD);

    // 7. fp16 attention
    k_attn_tc<<<BB * HH, 512, ATT_SMEM>>>();

    // 8. out GEMM
    k_gemm16<<<dim3(NC / 128, 2), 512, GEMM_SMEM>>>(ao, wo, out_b, p_o2, nullptr,
                                                    NC, DD, DD);

    // 9. cx = LN(cx0 + o2)
    k_cn<<<NC, 256>>>(cn_g, cn_b, cxp);

    // 10. scores
    k_score2<<<256, 256, 65536>>>(cxp, mlp_w1, mlp_b1, mlp_w2, mlp_b2);

    // 11. segment softmax + pool
    k_pool<<<BB, 512>>>(cxp, alphap, drug);
}

// round 17
// speedup vs baseline: 1.0208x; 1.0208x over previous
#include <cuda_runtime.h>
#include <cuda_bf16.h>
#include <cuda_fp16.h>
#include <math.h>
#include <stdint.h>

#define NA 131072
#define NC 32768
#define BB 128
#define MM 256
#define EE 262144
#define DD 256
#define HH 8
#define CC 32
#define PEK 64
#define Q3 (3 * DD)

// ---------------- scratch ----------------
__device__ float g_pe[NC * DD];
__device__ float g_hx[NC * DD];
__device__ float g_cx0[NC * DD];
__device__ float g_o2[NC * DD];
__device__ float g_score[NC * HH];
__device__ int g_cnt[NC];
__device__ int g_off[NC + 1];
__device__ int g_cur[NC];
__device__ int g_adj[EE];
__device__ int g_bsum[32];
__device__ __half g_ape16[NC * PEK];
__device__ __half g_wpe16[DD * PEK];
__device__ __half g_agg16[NC * DD];
__device__ __half g_watom16[DD * DD];
__device__ __half g_acx16[NC * DD];
__device__ __half g_win16[3 * DD * DD];
__device__ __half g_qkv16[NC * Q3];
__device__ __half g_ao16[NC * DD];
__device__ __half g_wout16[DD * DD];

// ---------------- block reductions (256 threads) ----------------
__device__ __forceinline__ float blk_sum(float v, float* sh8) {
    int t = threadIdx.x;
    int lane = t & 31, w = t >> 5;
#pragma unroll
    for (int o = 16; o > 0; o >>= 1) v += __shfl_xor_sync(0xffffffffu, v, o);
    if (lane == 0) sh8[w] = v;
    __syncthreads();
    float tot = sh8[0];
#pragma unroll
    for (int i = 1; i < 8; i++) tot += sh8[i];
    __syncthreads();
    return tot;
}

// 512-thread variants
__device__ __forceinline__ float blk_sum16(float v, float* sh16) {
    int t = threadIdx.x;
    int lane = t & 31, w = t >> 5;
#pragma unroll
    for (int o = 16; o > 0; o >>= 1) v += __shfl_xor_sync(0xffffffffu, v, o);
    if (lane == 0) sh16[w] = v;
    __syncthreads();
    float tot = sh16[0];
#pragma unroll
    for (int i = 1; i < 16; i++) tot += sh16[i];
    __syncthreads();
    return tot;
}

__device__ __forceinline__ float blk_max16(float v, float* sh16) {
    int t = threadIdx.x;
    int lane = t & 31, w = t >> 5;
#pragma unroll
    for (int o = 16; o > 0; o >>= 1) v = fmaxf(v, __shfl_xor_sync(0xffffffffu, v, o));
    if (lane == 0) sh16[w] = v;
    __syncthreads();
    float tot = sh16[0];
#pragma unroll
    for (int i = 1; i < 16; i++) tot = fmaxf(tot, sh16[i]);
    __syncthreads();
    return tot;
}

__device__ __forceinline__ uint32_t pack_h2(float a, float b) {
    __half2 h = __floats2half2_rn(a, b);
    return *(uint32_t*)&h;
}

// ---------------- fused weight/pe conversion + cnt zeroing ----------------
__global__ void k_split_all(const float* __restrict__ pe_w, const float* __restrict__ atom_w,
                            const float* __restrict__ in_w, const float* __restrict__ out_w,
                            const float* __restrict__ clique_pe) {
    int i = blockIdx.x * 256 + threadIdx.x;
    if (i < NC) g_cnt[i] = 0;
    const int n0 = DD * PEK;
    const int n1 = n0 + DD * DD;
    const int n2 = n1 + 3 * DD * DD;
    const int n3 = n2 + DD * DD;
    const int n4 = n3 + NC * PEK;
    if (i >= n4) return;
    if (i < n0) {
        int r = i / PEK, c = i % PEK;
        float v = (c < 20) ? pe_w[r * 20 + c] : 0.f;
        g_wpe16[i] = __float2half(v);
    } else if (i < n1) g_watom16[i - n0] = __float2half(atom_w[i - n0]);
    else if (i < n2) g_win16[i - n1] = __float2half(in_w[i - n1]);
    else if (i < n3) g_wout16[i - n2] = __float2half(out_w[i - n2]);
    else {
        int j = i - n3;
        int r = j / PEK, c = j % PEK;
        float v = (c < 20) ? clique_pe[r * 20 + c] : 0.f;
        g_ape16[j] = __float2half(v);
    }
}

// ---------------- CSR build (separate kernels — round-15 layout) ----------------
__global__ void k_count(const int* __restrict__ col) {
    int e = blockIdx.x * 256 + threadIdx.x;
    if (e < EE) atomicAdd(&g_cnt[col[e]], 1);
}

// shuffle-based inclusive scan of 1024 elements (2 barriers)
__global__ void k_scan1() {
    __shared__ int wsum[32];
    int t = threadIdx.x, b = blockIdx.x;
    int lane = t & 31, w = t >> 5;
    int v = g_cnt[b * 1024 + t];
    int inc = v;
#pragma unroll
    for (int o = 1; o < 32; o <<= 1) {
        int u = __shfl_up_sync(0xffffffffu, inc, o);
        if (lane >= o) inc += u;
    }
    if (lane == 31) wsum[w] = inc;
    __syncthreads();
    if (w == 0) {
        int s = wsum[lane];
        int si = s;
#pragma unroll
        for (int o = 1; o < 32; o <<= 1) {
            int u = __shfl_up_sync(0xffffffffu, si, o);
            if (lane >= o) si += u;
        }
        wsum[lane] = si - s;  // exclusive warp offset
    }
    __syncthreads();
    int total = inc + wsum[w];
    g_off[b * 1024 + t] = total - v;  // exclusive within block
    if (t == 1023) g_bsum[b] = total;
}

__global__ void k_scan3() {
    __shared__ int sboff;
    __shared__ int stot;
    int b = blockIdx.x, t = threadIdx.x;
    if (t < 32) {
        int v = g_bsum[t];
        int inc = v;
#pragma unroll
        for (int o = 1; o < 32; o <<= 1) {
            int u = __shfl_up_sync(0xffffffffu, inc, o);
            if (t >= o) inc += u;
        }
        if (t == (b >> 2)) sboff = inc - v;
        if (t == 31) stot = inc;
    }
    __syncthreads();
    int i = b * 256 + t;
    int v = g_off[i] + sboff;
    g_off[i] = v;
    g_cur[i] = v;
    if (b == 0 && t == 0) g_off[NC] = stot;
}

__global__ void k_fill(const int* __restrict__ row, const int* __restrict__ col) {
    int e = blockIdx.x * 256 + threadIdx.x;
    if (e < EE) {
        int c = col[e];
        int pos = atomicAdd(&g_cur[c], 1);
        g_adj[pos] = row[e];
    }
}

__global__ void __launch_bounds__(256) k_gather(const float* __restrict__ x) {
    __shared__ float red[4][DD];
    int c = blockIdx.x;
    int t = threadIdx.x;
    int lane4 = t & 63;
    int sl = t >> 6;
    int s = g_off[c], e2 = g_off[c + 1];
    float4 acc = {0.f, 0.f, 0.f, 0.f};
    for (int j = s + sl; j < e2; j += 4) {
        int r = g_adj[j];
        float4 v = *(const float4*)(x + (size_t)r * DD + lane4 * 4);
        acc.x += v.x; acc.y += v.y; acc.z += v.z; acc.w += v.w;
    }
    *(float4*)&red[sl][lane4 * 4] = acc;
    __syncthreads();
    float tot = red[0][t] + red[1][t] + red[2][t] + red[3][t];
    float dg = (float)(e2 - s);
    tot /= fmaxf(dg, 1.f);
    g_agg16[(size_t)c * DD + t] = __float2half(tot);
}

// ---------------- HMMA primitives ----------------
__device__ __forceinline__ void ldsm4(uint32_t& r0, uint32_t& r1, uint32_t& r2, uint32_t& r3,
                                      const void* p) {
    uint32_t addr = (uint32_t)__cvta_generic_to_shared(p);
    asm volatile("ldmatrix.sync.aligned.m8n8.x4.shared.b16 {%0,%1,%2,%3}, [%4];"
                 : "=r"(r0), "=r"(r1), "=r"(r2), "=r"(r3)
                 : "r"(addr));
}

__device__ __forceinline__ void mma16816h(float* d, const uint32_t* a, const uint32_t* b) {
    asm volatile(
        "mma.sync.aligned.m16n8k16.row.col.f32.f16.f16.f32 "
        "{%0,%1,%2,%3},{%4,%5,%6,%7},{%8,%9},{%0,%1,%2,%3};"
        : "+f"(d[0]), "+f"(d[1]), "+f"(d[2]), "+f"(d[3])
        : "r"(a[0]), "r"(a[1]), "r"(a[2]), "r"(a[3]), "r"(b[0]), "r"(b[1]));
}

#define CP16(dst, src) \
    asm volatile("cp.async.cg.shared.global [%0], [%1], 16;" :: "r"(dst), "l"(src) : "memory")
#define CP_COMMIT() asm volatile("cp.async.commit_group;" ::: "memory")
#define CP_WAIT0() asm volatile("cp.async.wait_group 0;" ::: "memory")

#define SST 72
#define GEMM_SMEM (2 * 2 * 128 * SST * 2)

// ---------------- fp16 single-pass GEMM core (K-chunk 64) ----------------
__device__ __forceinline__ void gemm16_body(
    const __half* __restrict__ A, const __half* __restrict__ W,
    const float* __restrict__ bias, float* __restrict__ C,
    __half* __restrict__ Ch, int M, int K, int i0, int j0, __half* sbuf) {
    uint32_t sbase = (uint32_t)__cvta_generic_to_shared(sbuf);
    int tid = threadIdx.x;
    int lane = tid & 31, wid = tid >> 5;
    int wm = wid >> 2, wn = wid & 3;
    int mb = wm * 32, nb = wn * 32;

    float d[2][4][4];
#pragma unroll
    for (int mi = 0; mi < 2; mi++)
#pragma unroll
        for (int ni = 0; ni < 4; ni++)
#pragma unroll
            for (int e = 0; e < 4; e++) d[mi][ni][e] = 0.f;

    int nch = K >> 6;

#pragma unroll
    for (int i = 0; i < 4; i++) {
        int task = tid + i * 512;
        int ck = task & 7;
        int row = (task >> 3) & 127;
        int mat = task >> 10;
        const __half* src = mat ? (W + (size_t)(j0 + row) * K) : (A + (size_t)(i0 + row) * K);
        uint32_t dst = sbase + (uint32_t)((mat * 128 + row) * SST + ck * 8) * 2u;
        CP16(dst, src + ck * 8);
    }
    CP_COMMIT();

    for (int ch = 0; ch < nch; ch++) {
        int stage = ch & 1;
        CP_WAIT0();
        __syncthreads();
        if (ch + 1 < nch) {
            int kt = (ch + 1) << 6;
            int ns = (ch + 1) & 1;
#pragma unroll
            for (int i = 0; i < 4; i++) {
                int task = tid + i * 512;
                int ck = task & 7;
                int row = (task >> 3) & 127;
                int mat = task >> 10;
                const __half* src =
                    mat ? (W + (size_t)(j0 + row) * K) : (A + (size_t)(i0 + row) * K);
                uint32_t dst =
                    sbase + (uint32_t)(((ns * 2 + mat) * 128 + row) * SST + ck * 8) * 2u;
                CP16(dst, src + kt + ck * 8);
            }
            CP_COMMIT();
        }

        const __half* tA = sbuf + (stage * 2 + 0) * 128 * SST;
        const __half* tW = sbuf + (stage * 2 + 1) * 128 * SST;

#pragma unroll
        for (int ks = 0; ks < 4; ks++) {
            int k0 = ks * 16;
            uint32_t afr[2][4];
            uint32_t bfr[4][2];
#pragma unroll
            for (int mi = 0; mi < 2; mi++) {
                const __half* p =
                    tA + (mb + mi * 16 + (lane & 15)) * SST + k0 + (lane >> 4) * 8;
                ldsm4(afr[mi][0], afr[mi][1], afr[mi][2], afr[mi][3], p);
            }
#pragma unroll
            for (int np = 0; np < 2; np++) {
                const __half* p =
                    tW + (nb + np * 16 + (lane & 7) + ((lane >> 4) << 3)) * SST + k0 +
                    (((lane >> 3) & 1) << 3);
                uint32_t r0, r1, r2, r3;
                ldsm4(r0, r1, r2, r3, p);
                bfr[np * 2][0] = r0; bfr[np * 2][1] = r1;
                bfr[np * 2 + 1][0] = r2; bfr[np * 2 + 1][1] = r3;
            }
#pragma unroll
            for (int mi = 0; mi < 2; mi++)
#pragma unroll
                for (int ni = 0; ni < 4; ni++) mma16816h(d[mi][ni], afr[mi], bfr[ni]);
        }
        __syncthreads();
    }

#pragma unroll
    for (int mi = 0; mi < 2; mi++) {
#pragma unroll
        for (int ni = 0; ni < 4; ni++) {
            int row = i0 + mb + mi * 16 + (lane >> 2);
            int colc = j0 + nb + ni * 8 + (lane & 3) * 2;
            float b0 = bias ? bias[colc] : 0.f;
            float b1 = bias ? bias[colc + 1] : 0.f;
            float v00 = d[mi][ni][0] + b0, v01 = d[mi][ni][1] + b1;
            float v10 = d[mi][ni][2] + b0, v11 = d[mi][ni][3] + b1;
            size_t ix = (size_t)row * M + colc;
            size_t ix2 = ix + (size_t)8 * M;
            if (Ch) {
                *(uint32_t*)&Ch[ix] = pack_h2(v00, v01);
                *(uint32_t*)&Ch[ix2] = pack_h2(v10, v11);
            } else {
                C[ix] = v00;
                C[ix + 1] = v01;
                C[ix2] = v10;
                C[ix2 + 1] = v11;
            }
        }
    }
}

__global__ void __launch_bounds__(512, 2) k_gemm16(
    const __half* __restrict__ A, const __half* __restrict__ W,
    const float* __restrict__ bias, float* __restrict__ C,
    __half* __restrict__ Ch, int N, int M, int K) {
    extern __shared__ __half sbuf[];
    gemm16_body(A, W, bias, C, Ch, M, K, blockIdx.x * 128, blockIdx.y * 128, sbuf);
}

__global__ void __launch_bounds__(512, 2) k_gemm16_dual(
    const __half* __restrict__ Aat, const __half* __restrict__ Wat,
    const __half* __restrict__ Ape, const __half* __restrict__ Wpe) {
    extern __shared__ __half sbuf[];
    int y = blockIdx.y;
    if (y < 2) {
        gemm16_body(Aat, Wat, nullptr, g_hx, nullptr, DD, DD, blockIdx.x * 128, y * 128, sbuf);
    } else {
        gemm16_body(Ape, Wpe, nullptr, g_pe, nullptr, DD, PEK, blockIdx.x * 128,
                    (y - 2) * 128, sbuf);
    }
}

// ---------------- cx0 ----------------
__global__ void k_cx0(const float* __restrict__ clique_x,
                      const float* __restrict__ pe_g, const float* __restrict__ pe_b,
                      const float* __restrict__ atom_g, const float* __restrict__ atom_b) {
    __shared__ float sh8[8];
    int n = blockIdx.x, t = threadIdx.x;
    size_t idx = (size_t)n * DD + t;

    float pv = g_pe[idx];
    float mu = blk_sum(pv, sh8) * (1.f / DD);
    float dv = pv - mu;
    float var = blk_sum(dv * dv, sh8) * (1.f / DD);
    float pen = dv * rsqrtf(var + 1e-5f) * pe_g[t] + pe_b[t];

    float hv = g_hx[idx];
    mu = blk_sum(hv, sh8) * (1.f / DD);
    dv = hv - mu;
    var = blk_sum(dv * dv, sh8) * (1.f / DD);
    float hxn = dv * rsqrtf(var + 1e-5f) * atom_g[t] + atom_b[t];

    float v = clique_x[idx] + pen + hxn;
    g_cx0[idx] = v;
    g_acx16[idx] = __float2half(v);
}

// ---------------- fp16 single-pass flash attention ----------------
#define QS 40
#define VS 264
#define ATT_SMEM ((2 * 256 * QS + 32 * VS) * 2)

__global__ void __launch_bounds__(512, 2) k_attn_tc() {
    extern __shared__ __half smh[];
    __half* qh = smh;
    __half* kh = smh + 256 * QS;
    __half* vt = smh + 2 * 256 * QS;

    int bh = blockIdx.x, b = bh >> 3, hh = bh & 7;
    int t = threadIdx.x, lane = t & 31, w = t >> 5;
    int n0 = b * MM;

    {
        int j = t >> 1;
        int c0 = (t & 1) * 16;
        size_t src = (size_t)(n0 + j) * Q3 + hh * CC + c0;
        uint32_t dq = (uint32_t)__cvta_generic_to_shared(qh + j * QS + c0);
        uint32_t dk = (uint32_t)__cvta_generic_to_shared(kh + j * QS + c0);
        CP16(dq, g_qkv16 + src);
        CP16(dq + 16, g_qkv16 + src + 8);
        CP16(dk, g_qkv16 + src + DD);
        CP16(dk + 16, g_qkv16 + src + DD + 8);
        uint4 v0 = *(const uint4*)(g_qkv16 + src + 2 * DD);
        uint4 v1 = *(const uint4*)(g_qkv16 + src + 2 * DD + 8);
        const __half* vv0 = (const __half*)&v0;
        const __half* vv1 = (const __half*)&v1;
#pragma unroll
        for (int e = 0; e < 8; e++) {
            vt[(c0 + e) * VS + j] = vv0[e];
            vt[(c0 + 8 + e) * VS + j] = vv1[e];
        }
    }
    CP_COMMIT();
    CP_WAIT0();
    __syncthreads();

    int mb = w * 16;

    uint32_t aq[2][4];
#pragma unroll
    for (int ks = 0; ks < 2; ks++) {
        const __half* p = qh + (mb + (lane & 15)) * QS + ks * 16 + (lane >> 4) * 8;
        ldsm4(aq[ks][0], aq[ks][1], aq[ks][2], aq[ks][3], p);
    }

    float o[4][4];
#pragma unroll
    for (int ni = 0; ni < 4; ni++)
#pragma unroll
        for (int e = 0; e < 4; e++) o[ni][e] = 0.f;
    float mrow[2] = {-INFINITY, -INFINITY};
    float lrow[2] = {0.f, 0.f};

    const float scale = 0.17677669529663687f;

#pragma unroll 1
    for (int ck = 0; ck < 8; ck++) {
        float s[4][4];
#pragma unroll
        for (int nj = 0; nj < 4; nj++)
#pragma unroll
            for (int e = 0; e < 4; e++) s[nj][e] = 0.f;

#pragma unroll
        for (int ks = 0; ks < 2; ks++) {
            uint32_t bk[4][2];
#pragma unroll
            for (int np = 0; np < 2; np++) {
                const __half* p =
                    kh + (ck * 32 + np * 16 + (lane & 7) + ((lane >> 4) << 3)) * QS +
                    ks * 16 + (((lane >> 3) & 1) << 3);
                uint32_t r0, r1, r2, r3;
                ldsm4(r0, r1, r2, r3, p);
                bk[np * 2][0] = r0; bk[np * 2][1] = r1;
                bk[np * 2 + 1][0] = r2; bk[np * 2 + 1][1] = r3;
            }
#pragma unroll
            for (int nj = 0; nj < 4; nj++) mma16816h(s[nj], aq[ks], bk[nj]);
        }

#pragma unroll
        for (int rh = 0; rh < 2; rh++) {
            float cm = -INFINITY;
#pragma unroll
            for (int nj = 0; nj < 4; nj++) {
                s[nj][rh * 2] *= scale;
                s[nj][rh * 2 + 1] *= scale;
                cm = fmaxf(cm, fmaxf(s[nj][rh * 2], s[nj][rh * 2 + 1]));
            }
            cm = fmaxf(cm, __shfl_xor_sync(0xffffffffu, cm, 1));
            cm = fmaxf(cm, __shfl_xor_sync(0xffffffffu, cm, 2));
            float nm = fmaxf(mrow[rh], cm);
            float corr = __expf(mrow[rh] - nm);
            mrow[rh] = nm;
            float ps = 0.f;
#pragma unroll
            for (int nj = 0; nj < 4; nj++) {
                float p0 = __expf(s[nj][rh * 2] - nm);
                float p1 = __expf(s[nj][rh * 2 + 1] - nm);
                s[nj][rh * 2] = p0;
                s[nj][rh * 2 + 1] = p1;
                ps += p0 + p1;
            }
            lrow[rh] = lrow[rh] * corr + ps;
#pragma unroll
            for (int ni = 0; ni < 4; ni++) {
                o[ni][rh * 2] *= corr;
                o[ni][rh * 2 + 1] *= corr;
            }
        }

#pragma unroll
        for (int kk = 0; kk < 2; kk++) {
            uint32_t bv[4][2];
#pragma unroll
            for (int ng = 0; ng < 2; ng++) {
                const __half* p =
                    vt + (ng * 16 + (lane & 7) + ((lane >> 4) << 3)) * VS + ck * 32 +
                    kk * 16 + (((lane >> 3) & 1) << 3);
                uint32_t r0, r1, r2, r3;
                ldsm4(r0, r1, r2, r3, p);
                bv[ng * 2][0] = r0; bv[ng * 2][1] = r1;
                bv[ng * 2 + 1][0] = r2; bv[ng * 2 + 1][1] = r3;
            }
            uint32_t pa[4];
#pragma unroll
            for (int half = 0; half < 2; half++) {
                int nj = kk * 2 + half;
#pragma unroll
                for (int e = 0; e < 2; e++)
                    pa[half * 2 + e] = pack_h2(s[nj][e * 2], s[nj][e * 2 + 1]);
            }
#pragma unroll
            for (int ni = 0; ni < 4; ni++) mma16816h(o[ni], pa, bv[ni]);
        }
    }

    float linv[2];
#pragma unroll
    for (int rh = 0; rh < 2; rh++) {
        float l = lrow[rh];
        l += __shfl_xor_sync(0xffffffffu, l, 1);
        l += __shfl_xor_sync(0xffffffffu, l, 2);
        linv[rh] = 1.f / l;
    }

#pragma unroll
    for (int ni = 0; ni < 4; ni++) {
        int row = mb + (lane >> 2);
        int chc = hh * CC + ni * 8 + (lane & 3) * 2;
        size_t idx = (size_t)(n0 + row) * DD + chc;
        *(uint32_t*)&g_ao16[idx] = pack_h2(o[ni][0] * linv[0], o[ni][1] * linv[0]);
        *(uint32_t*)&g_ao16[idx + (size_t)8 * DD] =
            pack_h2(o[ni][2] * linv[1], o[ni][3] * linv[1]);
    }
}

// ---------------- cx = LN(cx0 + o2) ----------------
__global__ void k_cn(const float* __restrict__ cn_g, const float* __restrict__ cn_b,
                     float* __restrict__ cxp) {
    __shared__ float sh8[8];
    int n = blockIdx.x, t = threadIdx.x;
    size_t idx = (size_t)n * DD + t;
    float v = g_cx0[idx] + g_o2[idx];
    float mu = blk_sum(v, sh8) * (1.f / DD);
    float dv = v - mu;
    float var = blk_sum(dv * dv, sh8) * (1.f / DD);
    cxp[idx] = dv * rsqrtf(var + 1e-5f) * cn_g[t] + cn_b[t];
}

// ---------------- per-head MLP score ----------------
__global__ void __launch_bounds__(256) k_score2(const float* __restrict__ cxp,
                                                const float* __restrict__ mlp_w1,
                                                const float* __restrict__ mlp_b1,
                                                const float* __restrict__ mlp_w2,
                                                const float* __restrict__ mlp_b2) {
    extern __shared__ float w1s[];
    __shared__ float b1s[512], w2s[512], b2s[8];
    int t = threadIdx.x;
    for (int i = t; i < 16384; i += 256) w1s[i] = mlp_w1[i];
    for (int i = t; i < 512; i += 256) {
        b1s[i] = mlp_b1[i];
        w2s[i] = mlp_w2[i];
    }
    if (t < 8) b2s[t] = mlp_b2[t];
    __syncthreads();

    int h = t >> 5, lane = t & 31;
    int base = blockIdx.x * 128;
#pragma unroll 1
    for (int pass = 0; pass < 4; pass++) {
        int n = base + pass * 32 + lane;
        float sc[32];
        const float* p = cxp + (size_t)n * DD + h * 32;
#pragma unroll
        for (int c = 0; c < 32; c += 4) {
            float4 v4 = *(const float4*)(p + c);
            sc[c] = v4.x; sc[c + 1] = v4.y; sc[c + 2] = v4.z; sc[c + 3] = v4.w;
        }
        float ssum = b2s[h];
#pragma unroll 4
        for (int d = 0; d < 64; d++) {
            float a = b1s[h * 64 + d];
            const float4* wr4 = (const float4*)&w1s[(h * 64 + d) * 32];
#pragma unroll
            for (int cc = 0; cc < 8; cc++) {
                float4 wv = wr4[cc];
                a += sc[cc * 4] * wv.x + sc[cc * 4 + 1] * wv.y + sc[cc * 4 + 2] * wv.z +
                     sc[cc * 4 + 3] * wv.w;
            }
            a = fmaxf(a, 0.f);
            ssum += a * w2s[h * 64 + d];
        }
        g_score[(size_t)n * HH + h] = ssum;
    }
}

// ---------------- segment softmax + pooling (512 threads) ----------------
__global__ void __launch_bounds__(512) k_pool(const float* __restrict__ cxp,
                                              float* __restrict__ alphap,
                                              float* __restrict__ drug) {
    __shared__ float sh16[16];
    __shared__ float al[MM * HH];
    __shared__ float part[2][DD];
    int b = blockIdx.x, t = threadIdx.x;
    int tq = t & 255;
    int n = b * MM + tq;
    float sc[HH];
    if (t < 256) {
#pragma unroll
        for (int h = 0; h < HH; h++) sc[h] = g_score[(size_t)n * HH + h];
    } else {
#pragma unroll
        for (int h = 0; h < HH; h++) sc[h] = -INFINITY;
    }
#pragma unroll
    for (int h = 0; h < HH; h++) {
        float mx = blk_max16(sc[h], sh16);
        float e = (t < 256) ? expf(sc[h] - mx) : 0.f;
        float s = blk_sum16(e, sh16);
        if (t < 256) {
            float a = e / s;
            al[tq * HH + h] = a;
            alphap[(size_t)n * HH + h] = a;
        }
    }
    __syncthreads();
    int g = t >> 8;
    int ch = t & 255;
    int h = ch >> 5;
    float acc = 0.f;
    int q0 = g * 128;
    for (int q = q0; q < q0 + 128; q++)
        acc += cxp[((size_t)b * MM + q) * DD + ch] * al[q * HH + h];
    part[g][ch] = acc;
    __syncthreads();
    if (t < 256) drug[(size_t)b * DD + t] = part[0][t] + part[1][t];
}

// ---------------- launch ----------------
extern "C" void kernel_launch(void* const* d_in, const int* in_sizes, int n_in,
                              void* d_out, int out_size) {
    const float* x         = (const float*)d_in[0];
    const float* clique_x  = (const float*)d_in[1];
    const float* clique_pe = (const float*)d_in[2];
    const int*   row       = (const int*)d_in[3];
    const int*   col       = (const int*)d_in[4];
    const float* pe_w   = (const float*)d_in[6];
    const float* pe_g   = (const float*)d_in[7];
    const float* pe_b   = (const float*)d_in[8];
    const float* atom_w = (const float*)d_in[9];
    const float* atom_g = (const float*)d_in[10];
    const float* atom_b = (const float*)d_in[11];
    const float* in_w   = (const float*)d_in[12];
    const float* in_b   = (const float*)d_in[13];
    const float* out_w  = (const float*)d_in[14];
    const float* out_b  = (const float*)d_in[15];
    const float* cn_g   = (const float*)d_in[16];
    const float* cn_b   = (const float*)d_in[17];
    const float* mlp_w1 = (const float*)d_in[18];
    const float* mlp_b1 = (const float*)d_in[19];
    const float* mlp_w2 = (const float*)d_in[20];
    const float* mlp_b2 = (const float*)d_in[21];

    float* out = (float*)d_out;
    float* drug   = out;
    float* cxp    = out + (size_t)BB * DD;
    float* alphap = cxp + (size_t)NC * DD;

    float* p_o2;
    cudaGetSymbolAddress((void**)&p_o2, g_o2);
    __half *ape, *wpe, *agg, *wat, *acx, *win, *qkv, *ao, *wo;
    cudaGetSymbolAddress((void**)&ape, g_ape16);
    cudaGetSymbolAddress((void**)&wpe, g_wpe16);
    cudaGetSymbolAddress((void**)&agg, g_agg16);
    cudaGetSymbolAddress((void**)&wat, g_watom16);
    cudaGetSymbolAddress((void**)&acx, g_acx16);
    cudaGetSymbolAddress((void**)&win, g_win16);
    cudaGetSymbolAddress((void**)&qkv, g_qkv16);
    cudaGetSymbolAddress((void**)&ao, g_ao16);
    cudaGetSymbolAddress((void**)&wo, g_wout16);

    cudaFuncSetAttribute(k_score2, cudaFuncAttributeMaxDynamicSharedMemorySize, 65536);
    cudaFuncSetAttribute(k_gemm16, cudaFuncAttributeMaxDynamicSharedMemorySize, GEMM_SMEM);
    cudaFuncSetAttribute(k_gemm16_dual, cudaFuncAttributeMaxDynamicSharedMemorySize, GEMM_SMEM);
    cudaFuncSetAttribute(k_attn_tc, cudaFuncAttributeMaxDynamicSharedMemorySize, ATT_SMEM);
    cudaFuncSetAttribute(k_attn_tc, cudaFuncAttributePreferredSharedMemoryCarveout, 100);

    const int splitN = DD * PEK + DD * DD + 3 * DD * DD + DD * DD + NC * PEK;

    // 1. fused conversions + cnt zero
    k_split_all<<<(splitN + 255) / 256, 256>>>(pe_w, atom_w, in_w, out_w, clique_pe);

    // 2-5. CSR build + gather (separate kernels; shuffle-scan scan1)
    k_count<<<EE / 256, 256>>>(col);
    k_scan1<<<32, 1024>>>();
    k_scan3<<<NC / 256, 256>>>();
    k_fill<<<EE / 256, 256>>>(row, col);
    k_gather<<<NC, 256>>>(x);

    // 6. merged atom + pe GEMM (K-chunk 64)
    k_gemm16_dual<<<dim3(NC / 128, 4), 512, GEMM_SMEM>>>(agg, wat, ape, wpe);

    // 7. cx0 (+ fp16 store)
    k_cx0<<<NC, 256>>>(clique_x, pe_g, pe_b, atom_g, atom_b);

    // 8. qkv GEMM — fp16 in/out
    k_gemm16<<<dim3(NC / 128, 6), 512, GEMM_SMEM>>>(acx, win, in_b, nullptr, qkv,
                                                    NC, 3 * DD, DD);

    // 9. fp16 attention
    k_attn_tc<<<BB * HH, 512, ATT_SMEM>>>();

    // 10. out GEMM
    k_gemm16<<<dim3(NC / 128, 2), 512, GEMM_SMEM>>>(ao, wo, out_b, p_o2, nullptr,
                                                    NC, DD, DD);

    // 11. cx = LN(cx0 + o2)
    k_cn<<<NC, 256>>>(cn_g, cn_b, cxp);

    // 12. scores
    k_score2<<<256, 256, 65536>>>(cxp, mlp_w1, mlp_b1, mlp_w2, mlp_b2);

    // 13. segment softmax + pool
    k_pool<<<BB, 512>>>(cxp, alphap, drug);
}